// round 2
// baseline (speedup 1.0000x reference)
#include <cuda_runtime.h>

#define NE 1200000
#define NN 50000
#define DF 64
#define HID 32

__device__ int g_idx_is64;

// ---- packed f32x2 helpers (Blackwell sm_103a) ----
__device__ __forceinline__ unsigned long long pk2(float a, float b) {
    unsigned long long r;
    asm("mov.b64 %0, {%1, %2};" : "=l"(r) : "f"(a), "f"(b));
    return r;
}
__device__ __forceinline__ void upk2(unsigned long long v, float& a, float& b) {
    asm("mov.b64 {%0, %1}, %2;" : "=f"(a), "=f"(b) : "l"(v));
}
__device__ __forceinline__ unsigned long long fma2(unsigned long long a,
                                                   unsigned long long b,
                                                   unsigned long long c) {
    unsigned long long d;
    asm("fma.rn.f32x2 %0, %1, %2, %3;" : "=l"(d) : "l"(a), "l"(b), "l"(c));
    return d;
}

// Decide whether edge_index is int64 or int32 (JAX canonicalizes int64->int32
// unless x64 is enabled; metadata is ambiguous from in_sizes alone).
// If truly int64, every 8-byte value is in [0, NN). If int32, pairing two
// random int32 indices gives values >= 2^32 whenever the hi word != 0.
__global__ void probe_kernel(const long long* __restrict__ ei) {
    int ok64 = 1;
    for (int i = 0; i < 8; i++) {
        long long v = ei[i];
        if (v < 0 || v >= NN) ok64 = 0;
    }
    g_idx_is64 = ok64;
}

__global__ void zero_kernel(float* __restrict__ out, int n) {
    int i = blockIdx.x * blockDim.x + threadIdx.x;
    if (i < n) out[i] = 0.0f;
}

__global__ __launch_bounds__(256, 2)
void edge_mlp_kernel(const float4* __restrict__ x4,
                     const void* __restrict__ ei_raw,
                     const float* __restrict__ u,
                     const float* __restrict__ W1,
                     const float* __restrict__ b1,
                     const float* __restrict__ W2,
                     const float* __restrict__ b2,
                     const float* __restrict__ W3,
                     const float* __restrict__ b3,
                     float* __restrict__ out)
{
    // Weights staged in shared; reads are warp-uniform (broadcast, 1 phase).
    __shared__ __align__(16) float W1s[128 * 32];   // 16 KB, row k contiguous over j
    __shared__ __align__(16) float W2s[32 * 32];    // 4 KB
    __shared__ __align__(8)  float b1s[32];
    __shared__ __align__(8)  float b2s[32];
    __shared__ float W3s[32];
    __shared__ float b3s;

    for (int i = threadIdx.x; i < 128 * 32 / 4; i += blockDim.x)
        ((float4*)W1s)[i] = ((const float4*)W1)[i];
    for (int i = threadIdx.x; i < 32 * 32 / 4; i += blockDim.x)
        ((float4*)W2s)[i] = ((const float4*)W2)[i];
    if (threadIdx.x < 32) {
        b1s[threadIdx.x] = b1[threadIdx.x];
        b2s[threadIdx.x] = b2[threadIdx.x];
        W3s[threadIdx.x] = W3[threadIdx.x];
    }
    if (threadIdx.x == 0) b3s = b3[0];
    __syncthreads();

    int e = blockIdx.x * blockDim.x + threadIdx.x;
    if (e >= NE) return;

    int row, col;
    if (g_idx_is64) {
        const long long* ei = (const long long*)ei_raw;
        row = (int)ei[e];
        col = (int)ei[NE + e];
    } else {
        const int* ei = (const int*)ei_raw;
        row = ei[e];
        col = ei[NE + e];
    }
    // Safety clamp (branch-free; correct data is already in range)
    row = min(max(row, 0), NN - 1);
    col = min(max(col, 0), NN - 1);

    // ---- layer 1: h = relu(concat(x[row], x[col]) @ W1 + b1) ----
    unsigned long long h[16];                // 32 fp32 accumulators as f32x2
    const unsigned long long* b1p = (const unsigned long long*)b1s;
    #pragma unroll
    for (int j = 0; j < 16; j++) h[j] = b1p[j];

    const unsigned long long* W1p = (const unsigned long long*)W1s;

    #pragma unroll 1
    for (int half = 0; half < 2; half++) {
        int node = half ? col : row;
        const float4* xp = x4 + (long)node * (DF / 4);
        #pragma unroll 4
        for (int q = 0; q < DF / 4; q++) {
            float4 xv = __ldg(xp + q);
            int kb = half * DF + q * 4;
            float vals[4] = {xv.x, xv.y, xv.z, xv.w};
            #pragma unroll
            for (int c = 0; c < 4; c++) {
                unsigned long long xx = pk2(vals[c], vals[c]);
                const unsigned long long* wrow = W1p + (size_t)(kb + c) * 16;
                #pragma unroll
                for (int j = 0; j < 16; j++)
                    h[j] = fma2(xx, wrow[j], h[j]);
            }
        }
    }

    float hr[32];
    #pragma unroll
    for (int j = 0; j < 16; j++) {
        float a, b;
        upk2(h[j], a, b);
        hr[2 * j]     = fmaxf(a, 0.0f);
        hr[2 * j + 1] = fmaxf(b, 0.0f);
    }

    // ---- layer 2: g = relu(hr @ W2 + b2) ----
    unsigned long long g[16];
    const unsigned long long* b2p = (const unsigned long long*)b2s;
    #pragma unroll
    for (int j = 0; j < 16; j++) g[j] = b2p[j];

    const unsigned long long* W2p = (const unsigned long long*)W2s;
    #pragma unroll 4
    for (int k = 0; k < HID; k++) {
        unsigned long long xx = pk2(hr[k], hr[k]);
        const unsigned long long* wrow = W2p + (size_t)k * 16;
        #pragma unroll
        for (int j = 0; j < 16; j++)
            g[j] = fma2(xx, wrow[j], g[j]);
    }

    // ---- layer 3: w = relu(g) @ W3 + b3 ----
    float w = b3s;
    #pragma unroll
    for (int j = 0; j < 16; j++) {
        float a, b;
        upk2(g[j], a, b);
        w = fmaf(fmaxf(a, 0.0f), W3s[2 * j],     w);
        w = fmaf(fmaxf(b, 0.0f), W3s[2 * j + 1], w);
    }

    // ---- scatter: f[row] += w * u[col] ----
    atomicAdd(out + row, w * u[col]);
}

extern "C" void kernel_launch(void* const* d_in, const int* in_sizes, int n_in,
                              void* d_out, int out_size) {
    const float* x  = (const float*)d_in[0];
    const void*  ei = d_in[1];
    const float* u  = (const float*)d_in[2];
    const float* W1 = (const float*)d_in[3];
    const float* b1 = (const float*)d_in[4];
    const float* W2 = (const float*)d_in[5];
    const float* b2 = (const float*)d_in[6];
    const float* W3 = (const float*)d_in[7];
    const float* b3 = (const float*)d_in[8];
    float* out = (float*)d_out;

    probe_kernel<<<1, 1>>>((const long long*)ei);
    zero_kernel<<<(NN + 255) / 256, 256>>>(out, NN);
    edge_mlp_kernel<<<(NE + 255) / 256, 256>>>(
        (const float4*)x, ei, u, W1, b1, W2, b2, W3, b3, out);
}

// round 3
// speedup vs baseline: 1.3866x; 1.3866x over previous
#include <cuda_runtime.h>

#define NE 1200000
#define NN 50000
#define DF 64
#define HID 32

__device__ int g_idx_is64;

// ---- packed f32x2 helpers (Blackwell sm_103a) ----
__device__ __forceinline__ unsigned long long pk2(float a, float b) {
    unsigned long long r;
    asm("mov.b64 %0, {%1, %2};" : "=l"(r) : "f"(a), "f"(b));
    return r;
}
__device__ __forceinline__ void upk2(unsigned long long v, float& a, float& b) {
    asm("mov.b64 {%0, %1}, %2;" : "=f"(a), "=f"(b) : "l"(v));
}
__device__ __forceinline__ unsigned long long fma2(unsigned long long a,
                                                   unsigned long long b,
                                                   unsigned long long c) {
    unsigned long long d;
    asm("fma.rn.f32x2 %0, %1, %2, %3;" : "=l"(d) : "l"(a), "l"(b), "l"(c));
    return d;
}

// Fused: zero the output AND detect edge_index dtype (JAX canonicalizes
// int64->int32 unless x64 mode; in_sizes can't disambiguate). Genuine int64
// data has every 8-byte value in [0, NN); int32 pairs read as 64-bit are
// >= 2^32 whenever the hi word != 0.
__global__ void init_kernel(const long long* __restrict__ ei,
                            float* __restrict__ out) {
    int i = blockIdx.x * blockDim.x + threadIdx.x;
    if (i < NN) out[i] = 0.0f;
    if (i == 0) {
        int ok64 = 1;
        for (int k = 0; k < 8; k++) {
            long long v = ei[k];
            if (v < 0 || v >= NN) ok64 = 0;
        }
        g_idx_is64 = ok64;
    }
}

// layer2 + layer3 for one edge; fully inlined/unrolled so hr/g stay in regs.
__device__ __forceinline__ float edge_tail(const float (&hr)[32],
                                           const float* __restrict__ W2s,
                                           const unsigned long long* __restrict__ b2p,
                                           const float* __restrict__ W3s,
                                           float b3v) {
    unsigned long long g[16];
    #pragma unroll
    for (int j = 0; j < 16; j++) g[j] = b2p[j];

    #pragma unroll 4
    for (int k = 0; k < HID; k++) {
        unsigned long long xx = pk2(hr[k], hr[k]);
        const ulonglong2* w2 = (const ulonglong2*)(W2s + k * 32);
        #pragma unroll
        for (int m = 0; m < 8; m++) {
            ulonglong2 wv = w2[m];
            g[2 * m]     = fma2(xx, wv.x, g[2 * m]);
            g[2 * m + 1] = fma2(xx, wv.y, g[2 * m + 1]);
        }
    }

    float w = b3v;
    #pragma unroll
    for (int j = 0; j < 16; j++) {
        float a, b;
        upk2(g[j], a, b);
        w = fmaf(fmaxf(a, 0.0f), W3s[2 * j],     w);
        w = fmaf(fmaxf(b, 0.0f), W3s[2 * j + 1], w);
    }
    return w;
}

__global__ __launch_bounds__(256, 2)
void edge_mlp_kernel(const float4* __restrict__ x4,
                     const void* __restrict__ ei_raw,
                     const float* __restrict__ u,
                     const float* __restrict__ W1,
                     const float* __restrict__ b1,
                     const float* __restrict__ W2,
                     const float* __restrict__ b2,
                     const float* __restrict__ W3,
                     const float* __restrict__ b3,
                     float* __restrict__ out)
{
    __shared__ __align__(16) float W1s[128 * 32];   // 16 KB
    __shared__ __align__(16) float W2s[32 * 32];    // 4 KB
    __shared__ __align__(16) float b1s[32];
    __shared__ __align__(16) float b2s[32];
    __shared__ float W3s[32];
    __shared__ float b3s;

    for (int i = threadIdx.x; i < 128 * 32 / 4; i += blockDim.x)
        ((float4*)W1s)[i] = ((const float4*)W1)[i];
    for (int i = threadIdx.x; i < 32 * 32 / 4; i += blockDim.x)
        ((float4*)W2s)[i] = ((const float4*)W2)[i];
    if (threadIdx.x < 32) {
        b1s[threadIdx.x] = b1[threadIdx.x];
        b2s[threadIdx.x] = b2[threadIdx.x];
        W3s[threadIdx.x] = W3[threadIdx.x];
    }
    if (threadIdx.x == 0) b3s = b3[0];
    __syncthreads();

    long e0 = (long)blockIdx.x * 512 + threadIdx.x;
    long e1 = e0 + 256;
    if (e0 >= NE) return;
    bool v1 = (e1 < NE);
    if (!v1) e1 = e0;   // duplicate work, atomic suppressed below

    int row0, col0, row1, col1;
    if (g_idx_is64) {
        const long long* ei = (const long long*)ei_raw;
        row0 = (int)ei[e0];      row1 = (int)ei[e1];
        col0 = (int)ei[NE + e0]; col1 = (int)ei[NE + e1];
    } else {
        const int* ei = (const int*)ei_raw;
        row0 = ei[e0];      row1 = ei[e1];
        col0 = ei[NE + e0]; col1 = ei[NE + e1];
    }
    row0 = min(max(row0, 0), NN - 1); col0 = min(max(col0, 0), NN - 1);
    row1 = min(max(row1, 0), NN - 1); col1 = min(max(col1, 0), NN - 1);

    // ---- layer 1 for BOTH edges: h = relu(concat(x[r], x[c]) @ W1 + b1) ----
    unsigned long long h0[16], h1[16];
    const unsigned long long* b1p = (const unsigned long long*)b1s;
    #pragma unroll
    for (int j = 0; j < 16; j++) { h0[j] = b1p[j]; h1[j] = b1p[j]; }

    #pragma unroll 1
    for (int half = 0; half < 2; half++) {
        int n0 = half ? col0 : row0;
        int n1 = half ? col1 : row1;
        const float4* xp0 = x4 + (long)n0 * (DF / 4);
        const float4* xp1 = x4 + (long)n1 * (DF / 4);
        #pragma unroll 2
        for (int q = 0; q < DF / 4; q++) {
            float4 a = __ldg(xp0 + q);
            float4 b = __ldg(xp1 + q);
            float av[4] = {a.x, a.y, a.z, a.w};
            float bv[4] = {b.x, b.y, b.z, b.w};
            #pragma unroll
            for (int c = 0; c < 4; c++) {
                unsigned long long xx0 = pk2(av[c], av[c]);
                unsigned long long xx1 = pk2(bv[c], bv[c]);
                int k = half * DF + q * 4 + c;
                const ulonglong2* w1 = (const ulonglong2*)(W1s + k * 32);
                #pragma unroll
                for (int m = 0; m < 8; m++) {
                    ulonglong2 wv = w1[m];           // LDS.128, broadcast
                    h0[2 * m]     = fma2(xx0, wv.x, h0[2 * m]);
                    h0[2 * m + 1] = fma2(xx0, wv.y, h0[2 * m + 1]);
                    h1[2 * m]     = fma2(xx1, wv.x, h1[2 * m]);
                    h1[2 * m + 1] = fma2(xx1, wv.y, h1[2 * m + 1]);
                }
            }
        }
    }

    float hr0[32], hr1[32];
    #pragma unroll
    for (int j = 0; j < 16; j++) {
        float a, b;
        upk2(h0[j], a, b);
        hr0[2 * j] = fmaxf(a, 0.0f); hr0[2 * j + 1] = fmaxf(b, 0.0f);
        upk2(h1[j], a, b);
        hr1[2 * j] = fmaxf(a, 0.0f); hr1[2 * j + 1] = fmaxf(b, 0.0f);
    }

    // ---- layers 2+3, sequential per edge (register pressure) ----
    const unsigned long long* b2p = (const unsigned long long*)b2s;
    float b3v = b3s;

    float w0 = edge_tail(hr0, W2s, b2p, W3s, b3v);
    atomicAdd(out + row0, w0 * __ldg(u + col0));

    float w1 = edge_tail(hr1, W2s, b2p, W3s, b3v);
    if (v1) atomicAdd(out + row1, w1 * __ldg(u + col1));
}

extern "C" void kernel_launch(void* const* d_in, const int* in_sizes, int n_in,
                              void* d_out, int out_size) {
    const float* x  = (const float*)d_in[0];
    const void*  ei = d_in[1];
    const float* u  = (const float*)d_in[2];
    const float* W1 = (const float*)d_in[3];
    const float* b1 = (const float*)d_in[4];
    const float* W2 = (const float*)d_in[5];
    const float* b2 = (const float*)d_in[6];
    const float* W3 = (const float*)d_in[7];
    const float* b3 = (const float*)d_in[8];
    float* out = (float*)d_out;

    init_kernel<<<(NN + 255) / 256, 256>>>((const long long*)ei, out);
    edge_mlp_kernel<<<(NE + 511) / 512, 256>>>(
        (const float4*)x, ei, u, W1, b1, W2, b2, W3, b3, out);
}

// round 4
// speedup vs baseline: 1.9798x; 1.4278x over previous
#include <cuda_runtime.h>

#define NE 1200000
#define NN 50000
#define DF 64
#define HID 32

__device__ int g_idx_is64;

// Weights in constant memory: warp-uniform reads go through the uniform
// constant port (LDCU, separate from L1tex) instead of smem LDS broadcasts.
__constant__ float cW1[2 * DF * HID];   // 16 KB, row k contiguous over j
__constant__ float cW2[HID * HID];      // 4 KB
__constant__ float cb1[HID];
__constant__ float cb2[HID];
__constant__ float cW3[HID];
__constant__ float cb3[1];

// ---- packed f32x2 helpers (Blackwell sm_103a) ----
__device__ __forceinline__ unsigned long long pk2(float a, float b) {
    unsigned long long r;
    asm("mov.b64 %0, {%1, %2};" : "=l"(r) : "f"(a), "f"(b));
    return r;
}
__device__ __forceinline__ void upk2(unsigned long long v, float& a, float& b) {
    asm("mov.b64 {%0, %1}, %2;" : "=f"(a), "=f"(b) : "l"(v));
}
__device__ __forceinline__ unsigned long long fma2(unsigned long long a,
                                                   unsigned long long b,
                                                   unsigned long long c) {
    unsigned long long d;
    asm("fma.rn.f32x2 %0, %1, %2, %3;" : "=l"(d) : "l"(a), "l"(b), "l"(c));
    return d;
}

// Fused: zero output + detect edge_index dtype (JAX canonicalizes int64->int32
// unless x64 mode). Genuine int64 has every 8-byte value in [0, NN).
__global__ void init_kernel(const long long* __restrict__ ei,
                            float* __restrict__ out) {
    int i = blockIdx.x * blockDim.x + threadIdx.x;
    if (i < NN) out[i] = 0.0f;
    if (i == 0) {
        int ok64 = 1;
        for (int k = 0; k < 8; k++) {
            long long v = ei[k];
            if (v < 0 || v >= NN) ok64 = 0;
        }
        g_idx_is64 = ok64;
    }
}

// layer2 + layer3 for one edge; hr/g stay in regs, W2/W3 from constant.
__device__ __forceinline__ float edge_tail(const float (&hr)[32]) {
    unsigned long long g[16];
    const unsigned long long* b2p = (const unsigned long long*)cb2;
    #pragma unroll
    for (int j = 0; j < 16; j++) g[j] = b2p[j];

    #pragma unroll 4
    for (int k = 0; k < HID; k++) {
        unsigned long long xx = pk2(hr[k], hr[k]);
        const ulonglong2* w2 = (const ulonglong2*)(cW2 + k * 32);
        #pragma unroll
        for (int m = 0; m < 8; m++) {
            ulonglong2 wv = w2[m];
            g[2 * m]     = fma2(xx, wv.x, g[2 * m]);
            g[2 * m + 1] = fma2(xx, wv.y, g[2 * m + 1]);
        }
    }

    float w = cb3[0];
    #pragma unroll
    for (int j = 0; j < 16; j++) {
        float a, b;
        upk2(g[j], a, b);
        w = fmaf(fmaxf(a, 0.0f), cW3[2 * j],     w);
        w = fmaf(fmaxf(b, 0.0f), cW3[2 * j + 1], w);
    }
    return w;
}

__global__ __launch_bounds__(256, 2)
void edge_mlp_kernel(const float4* __restrict__ x4,
                     const void* __restrict__ ei_raw,
                     const float* __restrict__ u,
                     float* __restrict__ out)
{
    long e0 = (long)blockIdx.x * 512 + threadIdx.x;
    long e1 = e0 + 256;
    if (e0 >= NE) return;
    bool v1 = (e1 < NE);
    if (!v1) e1 = e0;   // duplicate work, atomic suppressed below

    int row0, col0, row1, col1;
    if (g_idx_is64) {
        const long long* ei = (const long long*)ei_raw;
        row0 = (int)ei[e0];      row1 = (int)ei[e1];
        col0 = (int)ei[NE + e0]; col1 = (int)ei[NE + e1];
    } else {
        const int* ei = (const int*)ei_raw;
        row0 = ei[e0];      row1 = ei[e1];
        col0 = ei[NE + e0]; col1 = ei[NE + e1];
    }
    row0 = min(max(row0, 0), NN - 1); col0 = min(max(col0, 0), NN - 1);
    row1 = min(max(row1, 0), NN - 1); col1 = min(max(col1, 0), NN - 1);

    // ---- layer 1 for BOTH edges: h = relu(concat(x[r], x[c]) @ W1 + b1) ----
    unsigned long long h0[16], h1[16];
    const unsigned long long* b1p = (const unsigned long long*)cb1;
    #pragma unroll
    for (int j = 0; j < 16; j++) { h0[j] = b1p[j]; h1[j] = b1p[j]; }

    #pragma unroll 1
    for (int half = 0; half < 2; half++) {
        int n0 = half ? col0 : row0;
        int n1 = half ? col1 : row1;
        const float4* xp0 = x4 + (long)n0 * (DF / 4);
        const float4* xp1 = x4 + (long)n1 * (DF / 4);
        #pragma unroll 2
        for (int q = 0; q < DF / 4; q++) {
            float4 a = __ldg(xp0 + q);
            float4 b = __ldg(xp1 + q);
            float av[4] = {a.x, a.y, a.z, a.w};
            float bv[4] = {b.x, b.y, b.z, b.w};
            #pragma unroll
            for (int c = 0; c < 4; c++) {
                unsigned long long xx0 = pk2(av[c], av[c]);
                unsigned long long xx1 = pk2(bv[c], bv[c]);
                int k = half * DF + q * 4 + c;
                const ulonglong2* w1 = (const ulonglong2*)(cW1 + k * 32);
                #pragma unroll
                for (int m = 0; m < 8; m++) {
                    ulonglong2 wv = w1[m];           // LDCU.128 (uniform port)
                    h0[2 * m]     = fma2(xx0, wv.x, h0[2 * m]);
                    h0[2 * m + 1] = fma2(xx0, wv.y, h0[2 * m + 1]);
                    h1[2 * m]     = fma2(xx1, wv.x, h1[2 * m]);
                    h1[2 * m + 1] = fma2(xx1, wv.y, h1[2 * m + 1]);
                }
            }
        }
    }

    float hr0[32], hr1[32];
    #pragma unroll
    for (int j = 0; j < 16; j++) {
        float a, b;
        upk2(h0[j], a, b);
        hr0[2 * j] = fmaxf(a, 0.0f); hr0[2 * j + 1] = fmaxf(b, 0.0f);
        upk2(h1[j], a, b);
        hr1[2 * j] = fmaxf(a, 0.0f); hr1[2 * j + 1] = fmaxf(b, 0.0f);
    }

    // ---- layers 2+3, sequential per edge (register pressure) ----
    float w0 = edge_tail(hr0);
    atomicAdd(out + row0, w0 * __ldg(u + col0));

    float w1 = edge_tail(hr1);
    if (v1) atomicAdd(out + row1, w1 * __ldg(u + col1));
}

extern "C" void kernel_launch(void* const* d_in, const int* in_sizes, int n_in,
                              void* d_out, int out_size) {
    const float* x  = (const float*)d_in[0];
    const void*  ei = d_in[1];
    const float* u  = (const float*)d_in[2];
    const float* W1 = (const float*)d_in[3];
    const float* b1 = (const float*)d_in[4];
    const float* W2 = (const float*)d_in[5];
    const float* b2 = (const float*)d_in[6];
    const float* W3 = (const float*)d_in[7];
    const float* b3 = (const float*)d_in[8];
    float* out = (float*)d_out;

    // Device-to-device async copies into constant bank: graph-capturable.
    cudaMemcpyToSymbolAsync(cW1, W1, 2 * DF * HID * sizeof(float), 0,
                            cudaMemcpyDeviceToDevice, 0);
    cudaMemcpyToSymbolAsync(cW2, W2, HID * HID * sizeof(float), 0,
                            cudaMemcpyDeviceToDevice, 0);
    cudaMemcpyToSymbolAsync(cb1, b1, HID * sizeof(float), 0,
                            cudaMemcpyDeviceToDevice, 0);
    cudaMemcpyToSymbolAsync(cb2, b2, HID * sizeof(float), 0,
                            cudaMemcpyDeviceToDevice, 0);
    cudaMemcpyToSymbolAsync(cW3, W3, HID * sizeof(float), 0,
                            cudaMemcpyDeviceToDevice, 0);
    cudaMemcpyToSymbolAsync(cb3, b3, sizeof(float), 0,
                            cudaMemcpyDeviceToDevice, 0);

    init_kernel<<<(NN + 255) / 256, 256>>>((const long long*)ei, out);
    edge_mlp_kernel<<<(NE + 511) / 512, 256>>>(
        (const float4*)x, ei, u, out);
}